// round 3
// baseline (speedup 1.0000x reference)
#include <cuda_runtime.h>
#include <cuda_bf16.h>

// ChannelBlockImportanceGate: forward value == hard top-k block mask.
// features [8,256,132,132] f32, enabled int32. BLOCK=8 -> 17x17=289 blocks,
// keep = 72. Ties: lower flat index wins (lax.top_k).
//
// R3: memory-bound tuning. 128-thread CTAs @ occ 16 -> single wave (2048
// concurrent CTAs). Phase A linearized over (row, block) segments so all 32
// lanes load 32B/iter (2x MLP). Streaming cache hints. FP reduction tree
// bitwise identical to the R2-passing kernel.

#define HH   132
#define WW   132
#define NBX  17
#define NBLK 289
#define KEEP 72
#define NPIX (HH*WW)
#define NSEG (HH*NBX)      // 2244 row-block segments
#define NTHREADS 128

__global__ __launch_bounds__(NTHREADS, 16)
void gate_kernel(const float* __restrict__ in,
                 const int*  __restrict__ enabled,
                 float* __restrict__ out)
{
    const int bc = blockIdx.x;
    const long long base = (long long)bc * NPIX;
    const int tid  = threadIdx.x;
    const int warp = tid >> 5;
    const int lane = tid & 31;

    if (*enabled == 0) {
        float4 ones = make_float4(1.f, 1.f, 1.f, 1.f);
        float4* o4 = (float4*)(out + base);
        for (int p = tid; p < NPIX / 4; p += NTHREADS) o4[p] = ones;
        return;
    }

    __shared__ float rbs[NSEG];         // per-row 8-wide block partials
    __shared__ float pooled[NBLK];
    __shared__ float hardm[NBLK];
    __shared__ int   hist[32];
    __shared__ float wmin[4], wmax[4];
    __shared__ float s_minv, s_scale;
    __shared__ int   s_bb, s_chi, s_mcnt;
    __shared__ int   bblist[NBLK];

    if (tid < 32) hist[tid] = 0;
    if (tid == 0) s_mcnt = 0;

    const float4* src4 = (const float4*)(in + base);

    // ---- Phase A: each thread owns (row, bx) segments; all lanes load.
    // Segment s: row = s/17, bx = s%17; floats row*132 + bx*8 .. +7.
    // Sum tree identical to R2: ((ax+bx)+(az+bz))+((ay+by)+(aw+bw)).
    for (int s = tid; s < NSEG; s += NTHREADS) {
        int row = s / NBX;              // const-div -> mul/shift
        int bx  = s - row * NBX;
        int f4  = row * 33 + bx * 2;    // 33 float4 per row
        float4 a = __ldcs(src4 + f4);
        float4 b;
        if (bx < 16) b = __ldcs(src4 + f4 + 1);
        else         b = make_float4(0.f, 0.f, 0.f, 0.f);
        rbs[s] = ((fabsf(a.x) + fabsf(b.x)) + (fabsf(a.z) + fabsf(b.z)))
               + ((fabsf(a.y) + fabsf(b.y)) + (fabsf(a.w) + fabsf(b.w)));
    }
    __syncthreads();

    // ---- Phase B: block sums (linear over 8 rows, rows>=132 are pad) + min/max.
    float lmin = 3.4e38f, lmax = -3.4e38f;
    for (int b = tid; b < NBLK; b += NTHREADS) {
        int by = b / NBX;
        int bx = b - by * NBX;
        int y0 = by * 8;
        float s = 0.0f;
        #pragma unroll
        for (int r = 0; r < 8; r++) {
            int y = y0 + r;
            if (y < HH) s += rbs[y * NBX + bx];
        }
        pooled[b] = s;
        lmin = fminf(lmin, s);
        lmax = fmaxf(lmax, s);
    }
    #pragma unroll
    for (int off = 16; off > 0; off >>= 1) {
        lmin = fminf(lmin, __shfl_down_sync(0xffffffffu, lmin, off));
        lmax = fmaxf(lmax, __shfl_down_sync(0xffffffffu, lmax, off));
    }
    if (lane == 0) { wmin[warp] = lmin; wmax[warp] = lmax; }
    __syncthreads();

    if (warp == 0) {
        float mn = (lane < 4) ? wmin[lane] : 3.4e38f;
        float mx = (lane < 4) ? wmax[lane] : -3.4e38f;
        #pragma unroll
        for (int off = 2; off > 0; off >>= 1) {
            mn = fminf(mn, __shfl_down_sync(0xffffffffu, mn, off));
            mx = fmaxf(mx, __shfl_down_sync(0xffffffffu, mx, off));
        }
        if (lane == 0) {
            float r = mx - mn;
            s_minv  = mn;
            s_scale = (r > 0.0f) ? (32.0f / r) : 0.0f;
        }
    }
    __syncthreads();

    // ---- histogram
    {
        float minv = s_minv, scale = s_scale;
        for (int b = tid; b < NBLK; b += NTHREADS) {
            int bin = min((int)((pooled[b] - minv) * scale), 31);
            atomicAdd(&hist[bin], 1);
        }
    }
    __syncthreads();

    // ---- warp 0: suffix scan -> boundary bin bb, count strictly above (chi)
    if (warp == 0) {
        int cge = hist[lane];
        #pragma unroll
        for (int off = 1; off < 32; off <<= 1) {
            int t = __shfl_down_sync(0xffffffffu, cge, off);
            if (lane + off < 32) cge += t;
        }
        int cgt = __shfl_down_sync(0xffffffffu, cge, 1);
        if (lane == 31) cgt = 0;
        if (cgt < KEEP && cge >= KEEP) { s_bb = lane; s_chi = cgt; }
    }
    __syncthreads();

    // ---- classify; collect boundary-bin items
    {
        float minv = s_minv, scale = s_scale;
        int bb = s_bb;
        for (int b = tid; b < NBLK; b += NTHREADS) {
            int bin = min((int)((pooled[b] - minv) * scale), 31);
            if (bin > bb)      hardm[b] = 1.0f;
            else if (bin < bb) hardm[b] = 0.0f;
            else               bblist[atomicAdd(&s_mcnt, 1)] = b;
        }
    }
    __syncthreads();

    // ---- exact rank inside boundary bin (tie: lower index wins)
    {
        int m = s_mcnt;
        int budget = KEEP - s_chi;
        for (int it = tid; it < m; it += NTHREADS) {
            int i = bblist[it];
            float vi = pooled[i];
            int c = 0;
            for (int j = 0; j < m; j++) {
                int jj = bblist[j];
                float vj = pooled[jj];
                c += (vj > vi) || (vj == vi && jj < i);
            }
            hardm[i] = (c < budget) ? 1.0f : 0.0f;
        }
    }
    __syncthreads();

    // ---- Phase D: expand to pixels, float4 streaming stores
    for (int by = warp; by < NBX; by += 4) {
        float  mv  = hardm[by * NBX + (lane >> 1)];
        float  m16 = hardm[by * NBX + 16];
        float4 v4  = make_float4(mv, mv, mv, mv);
        float4 v16 = make_float4(m16, m16, m16, m16);
        int ylim = min(HH - by * 8, 8);
        float* obase = out + base + (by * 8) * WW;
        for (int r = 0; r < ylim; r++) {
            float* orow = obase + r * WW;
            __stcs((float4*)(orow + lane * 4), v4);
            if (lane == 0) __stcs((float4*)(orow + 128), v16);
        }
    }
}

extern "C" void kernel_launch(void* const* d_in, const int* in_sizes, int n_in,
                              void* d_out, int out_size)
{
    const float* features = (const float*)d_in[0];
    const int*   enabled  = (const int*)d_in[1];
    float* out = (float*)d_out;

    const int n_channels = out_size / NPIX;   // 2048
    gate_kernel<<<n_channels, NTHREADS>>>(features, enabled, out);
}

// round 4
// speedup vs baseline: 1.3426x; 1.3426x over previous
#include <cuda_runtime.h>
#include <cuda_bf16.h>

// ChannelBlockImportanceGate: forward value == hard top-k block mask.
// features [8,256,132,132] f32, enabled int32. BLOCK=8 -> 17x17=289 blocks,
// keep = 72. Ties: lower flat index wins (lax.top_k).
//
// R4: R2 structure (known-good), 2 channels per CTA: threads 0-127 run the
// full pipeline for channel 2*bid, threads 128-255 for 2*bid+1, fully
// concurrently. grid=1024 -> single wave at occ 8. FP reduction trees
// bitwise identical to the R2-passing kernel.

#define HH   132
#define WW   132
#define NBX  17
#define NBLK 289
#define KEEP 72
#define NPIX (HH*WW)
#define NTHREADS 256

__global__ __launch_bounds__(NTHREADS, 8)
void gate_kernel(const float* __restrict__ in,
                 const int*  __restrict__ enabled,
                 float* __restrict__ out,
                 int n_ch)
{
    const int tid   = threadIdx.x;
    const int half  = tid >> 7;          // which channel of the pair
    const int htid  = tid & 127;         // thread id within half
    const int warp  = tid >> 5;
    const int hwarp = warp & 3;          // warp id within half (0..3)
    const int lane  = tid & 31;
    const int ch    = blockIdx.x * 2 + half;
    const bool valid = (ch < n_ch);
    const long long base = (long long)ch * NPIX;

    if (*enabled == 0) {
        if (valid) {
            float4 ones = make_float4(1.f, 1.f, 1.f, 1.f);
            float4* o4 = (float4*)(out + base);
            for (int p = htid; p < NPIX / 4; p += 128) o4[p] = ones;
        }
        return;
    }

    __shared__ float rbs[2][HH * NBX];   // per-row 8-wide block partials
    __shared__ float pooled[2][NBLK];
    __shared__ float hardm[2][NBLK];
    __shared__ int   hist[2][32];
    __shared__ float wmin[8], wmax[8];
    __shared__ float s_minv[2], s_scale[2];
    __shared__ int   s_bb[2], s_chi[2], s_mcnt[2];
    __shared__ int   bblist[2][NBLK];

    if (tid < 64) hist[tid >> 5][tid & 31] = 0;
    if (tid < 2)  s_mcnt[tid] = 0;

    const float* src = in + base;

    // ---- Phase A: lane l (<17) owns block l of its row; 4 warps per half.
    // Sum tree identical to R2: ((ax+bx)+(az+bz))+((ay+by)+(aw+bw)).
    if (valid) {
        for (int y = hwarp; y < HH; y += 4) {
            if (lane < NBX) {
                const float* row = src + y * WW;
                float4 a = *(const float4*)(row + lane * 8);
                float4 b;
                if (lane < 16) b = *(const float4*)(row + lane * 8 + 4);
                else           b = make_float4(0.f, 0.f, 0.f, 0.f);
                float s = ((fabsf(a.x) + fabsf(b.x)) + (fabsf(a.z) + fabsf(b.z)))
                        + ((fabsf(a.y) + fabsf(b.y)) + (fabsf(a.w) + fabsf(b.w)));
                rbs[half][y * NBX + lane] = s;
            }
        }
    }
    __syncthreads();

    // ---- Phase B: block sums (linear over 8 rows, rows>=132 are pad) + min/max.
    float lmin = 3.4e38f, lmax = -3.4e38f;
    if (valid) {
        for (int b = htid; b < NBLK; b += 128) {
            int by = b / NBX;
            int bx = b - by * NBX;
            int y0 = by * 8;
            float s = 0.0f;
            #pragma unroll
            for (int r = 0; r < 8; r++) {
                int y = y0 + r;
                if (y < HH) s += rbs[half][y * NBX + bx];
            }
            pooled[half][b] = s;
            lmin = fminf(lmin, s);
            lmax = fmaxf(lmax, s);
        }
    }
    #pragma unroll
    for (int off = 16; off > 0; off >>= 1) {
        lmin = fminf(lmin, __shfl_down_sync(0xffffffffu, lmin, off));
        lmax = fmaxf(lmax, __shfl_down_sync(0xffffffffu, lmax, off));
    }
    if (lane == 0) { wmin[warp] = lmin; wmax[warp] = lmax; }
    __syncthreads();

    // ---- one scan warp per half (warps 0 and 4): global min/max -> bin scale
    if (hwarp == 0) {
        float mn = (lane < 4) ? wmin[half * 4 + lane] : 3.4e38f;
        float mx = (lane < 4) ? wmax[half * 4 + lane] : -3.4e38f;
        #pragma unroll
        for (int off = 2; off > 0; off >>= 1) {
            mn = fminf(mn, __shfl_down_sync(0xffffffffu, mn, off));
            mx = fmaxf(mx, __shfl_down_sync(0xffffffffu, mx, off));
        }
        if (lane == 0) {
            float r = mx - mn;
            s_minv[half]  = mn;
            s_scale[half] = (r > 0.0f) ? (32.0f / r) : 0.0f;
        }
    }
    __syncthreads();

    // ---- histogram per half
    if (valid) {
        float minv = s_minv[half], scale = s_scale[half];
        for (int b = htid; b < NBLK; b += 128) {
            int bin = min((int)((pooled[half][b] - minv) * scale), 31);
            atomicAdd(&hist[half][bin], 1);
        }
    }
    __syncthreads();

    // ---- suffix scan per half: boundary bin bb + count strictly above (chi)
    if (hwarp == 0) {
        int cge = hist[half][lane];
        #pragma unroll
        for (int off = 1; off < 32; off <<= 1) {
            int t = __shfl_down_sync(0xffffffffu, cge, off);
            if (lane + off < 32) cge += t;
        }
        int cgt = __shfl_down_sync(0xffffffffu, cge, 1);
        if (lane == 31) cgt = 0;
        if (cgt < KEEP && cge >= KEEP) { s_bb[half] = lane; s_chi[half] = cgt; }
    }
    __syncthreads();

    // ---- classify; collect boundary-bin items
    if (valid) {
        float minv = s_minv[half], scale = s_scale[half];
        int bb = s_bb[half];
        for (int b = htid; b < NBLK; b += 128) {
            int bin = min((int)((pooled[half][b] - minv) * scale), 31);
            if (bin > bb)      hardm[half][b] = 1.0f;
            else if (bin < bb) hardm[half][b] = 0.0f;
            else               bblist[half][atomicAdd(&s_mcnt[half], 1)] = b;
        }
    }
    __syncthreads();

    // ---- exact rank inside boundary bin (tie: lower index wins)
    if (valid) {
        int m = s_mcnt[half];
        int budget = KEEP - s_chi[half];
        for (int it = htid; it < m; it += 128) {
            int i = bblist[half][it];
            float vi = pooled[half][i];
            int c = 0;
            for (int j = 0; j < m; j++) {
                int jj = bblist[half][j];
                float vj = pooled[half][jj];
                c += (vj > vi) || (vj == vi && jj < i);
            }
            hardm[half][i] = (c < budget) ? 1.0f : 0.0f;
        }
    }
    __syncthreads();

    // ---- Phase D: expand to pixels, float4 stores
    if (valid) {
        for (int by = hwarp; by < NBX; by += 4) {
            float  mv  = hardm[half][by * NBX + (lane >> 1)];  // block for x=lane*4
            float  m16 = hardm[half][by * NBX + 16];           // tail x=128..131
            float4 v4  = make_float4(mv, mv, mv, mv);
            float4 v16 = make_float4(m16, m16, m16, m16);
            int ylim = min(HH - by * 8, 8);
            float* obase = out + base + (by * 8) * WW;
            for (int r = 0; r < ylim; r++) {
                float* orow = obase + r * WW;
                *(float4*)(orow + lane * 4) = v4;
                if (lane == 0) *(float4*)(orow + 128) = v16;
            }
        }
    }
}

extern "C" void kernel_launch(void* const* d_in, const int* in_sizes, int n_in,
                              void* d_out, int out_size)
{
    const float* features = (const float*)d_in[0];
    const int*   enabled  = (const int*)d_in[1];
    float* out = (float*)d_out;

    const int n_channels = out_size / NPIX;           // 2048
    const int grid = (n_channels + 1) / 2;            // 1024
    gate_kernel<<<grid, NTHREADS>>>(features, enabled, out, n_channels);
}

// round 5
// speedup vs baseline: 1.5219x; 1.1335x over previous
#include <cuda_runtime.h>
#include <cuda_bf16.h>

// ChannelBlockImportanceGate: forward value == hard top-k block mask.
// features [8,256,132,132] f32, enabled int32. BLOCK=8 -> 17x17=289 blocks,
// keep = 72. Ties: lower flat index wins (lax.top_k).
//
// R5: R2 structure (known-good 59.5us), Phase A unrolled over two rows with
// all 4 LDG.128 front-batched -> 2x outstanding load bytes per warp.
// FP reduction trees bitwise identical to the R2-passing kernel.

#define HH   132
#define WW   132
#define NBX  17
#define NBLK 289
#define KEEP 72
#define NPIX (HH*WW)
#define NTHREADS 256

__global__ __launch_bounds__(NTHREADS, 8)
void gate_kernel(const float* __restrict__ in,
                 const int*  __restrict__ enabled,
                 float* __restrict__ out)
{
    const int bc = blockIdx.x;
    const long long base = (long long)bc * NPIX;
    const int tid  = threadIdx.x;
    const int warp = tid >> 5;
    const int lane = tid & 31;

    if (*enabled == 0) {
        float4 ones = make_float4(1.f, 1.f, 1.f, 1.f);
        float4* o4 = (float4*)(out + base);
        for (int p = tid; p < NPIX / 4; p += NTHREADS) o4[p] = ones;
        return;
    }

    __shared__ float rbs[HH * NBX];     // per-row 8-wide block partials
    __shared__ float pooled[NBLK];
    __shared__ float hardm[NBLK];
    __shared__ int   hist[32];
    __shared__ float wmin[8], wmax[8];
    __shared__ float s_minv, s_scale;
    __shared__ int   s_bb, s_chi, s_mcnt;
    __shared__ int   bblist[NBLK];

    if (tid < 32) hist[tid] = 0;
    if (tid == 0) s_mcnt = 0;

    const float* src = in + base;

    // ---- Phase A: lane l (<17) owns block l of rows y and y+8; all four
    // LDG.128 issued before any consumption. Per-row sum tree identical to
    // R2: ((ax+bx)+(az+bz))+((ay+by)+(aw+bw)), with b==0 for lane 16.
    if (lane < NBX) {
        const int xo = lane * 8;
        const bool hasb = (lane < 16);
        for (int y = warp; y < HH; y += 16) {
            const int y2 = y + 8;
            const bool has2 = (y2 < HH);
            const float* row1 = src + y * WW + xo;
            const float* row2 = src + y2 * WW + xo;

            float4 a1 = *(const float4*)(row1);
            float4 b1 = hasb ? *(const float4*)(row1 + 4)
                             : make_float4(0.f, 0.f, 0.f, 0.f);
            float4 a2 = has2 ? *(const float4*)(row2)
                             : make_float4(0.f, 0.f, 0.f, 0.f);
            float4 b2 = (has2 && hasb) ? *(const float4*)(row2 + 4)
                                       : make_float4(0.f, 0.f, 0.f, 0.f);

            float s1 = ((fabsf(a1.x) + fabsf(b1.x)) + (fabsf(a1.z) + fabsf(b1.z)))
                     + ((fabsf(a1.y) + fabsf(b1.y)) + (fabsf(a1.w) + fabsf(b1.w)));
            float s2 = ((fabsf(a2.x) + fabsf(b2.x)) + (fabsf(a2.z) + fabsf(b2.z)))
                     + ((fabsf(a2.y) + fabsf(b2.y)) + (fabsf(a2.w) + fabsf(b2.w)));

            rbs[y * NBX + lane] = s1;
            if (has2) rbs[y2 * NBX + lane] = s2;
        }
    }
    __syncthreads();

    // ---- Phase B: block sums (linear over 8 rows, rows>=132 are pad) + min/max.
    float lmin = 3.4e38f, lmax = -3.4e38f;
    for (int b = tid; b < NBLK; b += NTHREADS) {
        int by = b / NBX;
        int bx = b - by * NBX;
        int y0 = by * 8;
        float s = 0.0f;
        #pragma unroll
        for (int r = 0; r < 8; r++) {
            int y = y0 + r;
            if (y < HH) s += rbs[y * NBX + bx];
        }
        pooled[b] = s;
        lmin = fminf(lmin, s);
        lmax = fmaxf(lmax, s);
    }
    #pragma unroll
    for (int off = 16; off > 0; off >>= 1) {
        lmin = fminf(lmin, __shfl_down_sync(0xffffffffu, lmin, off));
        lmax = fmaxf(lmax, __shfl_down_sync(0xffffffffu, lmax, off));
    }
    if (lane == 0) { wmin[warp] = lmin; wmax[warp] = lmax; }
    __syncthreads();

    // ---- warp 0: global min/max -> bin scale
    if (warp == 0) {
        float mn = (lane < 8) ? wmin[lane] : 3.4e38f;
        float mx = (lane < 8) ? wmax[lane] : -3.4e38f;
        #pragma unroll
        for (int off = 4; off > 0; off >>= 1) {
            mn = fminf(mn, __shfl_down_sync(0xffffffffu, mn, off));
            mx = fmaxf(mx, __shfl_down_sync(0xffffffffu, mx, off));
        }
        if (lane == 0) {
            float r = mx - mn;
            s_minv  = mn;
            s_scale = (r > 0.0f) ? (32.0f / r) : 0.0f;
        }
    }
    __syncthreads();

    // ---- histogram
    {
        float minv = s_minv, scale = s_scale;
        for (int b = tid; b < NBLK; b += NTHREADS) {
            int bin = min((int)((pooled[b] - minv) * scale), 31);
            atomicAdd(&hist[bin], 1);
        }
    }
    __syncthreads();

    // ---- warp 0: suffix scan -> boundary bin bb, count strictly above (chi)
    if (warp == 0) {
        int cge = hist[lane];
        #pragma unroll
        for (int off = 1; off < 32; off <<= 1) {
            int t = __shfl_down_sync(0xffffffffu, cge, off);
            if (lane + off < 32) cge += t;
        }
        int cgt = __shfl_down_sync(0xffffffffu, cge, 1);
        if (lane == 31) cgt = 0;
        if (cgt < KEEP && cge >= KEEP) { s_bb = lane; s_chi = cgt; }
    }
    __syncthreads();

    // ---- classify; collect boundary-bin items
    {
        float minv = s_minv, scale = s_scale;
        int bb = s_bb;
        for (int b = tid; b < NBLK; b += NTHREADS) {
            int bin = min((int)((pooled[b] - minv) * scale), 31);
            if (bin > bb)      hardm[b] = 1.0f;
            else if (bin < bb) hardm[b] = 0.0f;
            else               bblist[atomicAdd(&s_mcnt, 1)] = b;
        }
    }
    __syncthreads();

    // ---- exact rank inside boundary bin (tie: lower index wins)
    {
        int m = s_mcnt;
        int budget = KEEP - s_chi;
        for (int it = tid; it < m; it += NTHREADS) {
            int i = bblist[it];
            float vi = pooled[i];
            int c = 0;
            for (int j = 0; j < m; j++) {
                int jj = bblist[j];
                float vj = pooled[jj];
                c += (vj > vi) || (vj == vi && jj < i);
            }
            hardm[i] = (c < budget) ? 1.0f : 0.0f;
        }
    }
    __syncthreads();

    // ---- Phase D: expand to pixels, float4 stores
    for (int by = warp; by < NBX; by += 8) {
        float  mv  = hardm[by * NBX + (lane >> 1)];
        float  m16 = hardm[by * NBX + 16];
        float4 v4  = make_float4(mv, mv, mv, mv);
        float4 v16 = make_float4(m16, m16, m16, m16);
        int ylim = min(HH - by * 8, 8);
        float* obase = out + base + (by * 8) * WW;
        for (int r = 0; r < ylim; r++) {
            float* orow = obase + r * WW;
            *(float4*)(orow + lane * 4) = v4;
            if (lane == 0) *(float4*)(orow + 128) = v16;
        }
    }
}

extern "C" void kernel_launch(void* const* d_in, const int* in_sizes, int n_in,
                              void* d_out, int out_size)
{
    const float* features = (const float*)d_in[0];
    const int*   enabled  = (const int*)d_in[1];
    float* out = (float*)d_out;

    const int n_channels = out_size / NPIX;   // 2048
    gate_kernel<<<n_channels, NTHREADS>>>(features, enabled, out);
}

// round 6
// speedup vs baseline: 1.5838x; 1.0407x over previous
#include <cuda_runtime.h>
#include <cuda_bf16.h>
#include <cstdint>

// ChannelBlockImportanceGate: forward value == hard top-k block mask.
// features [8,256,132,132] f32, enabled int32. BLOCK=8 -> 17x17=289 blocks,
// keep = 72. Ties: lower flat index wins (lax.top_k).
//
// R6: cp.async (LDGSTS) double-buffered smem staging for the read side --
// outstanding load bytes no longer bounded by the register file. Reduction
// trees and row-sum order bitwise identical to all passing rounds.

#define HH   132
#define WW   132
#define NBX  17
#define NBLK 289
#define KEEP 72
#define NPIX (HH*WW)
#define NTHREADS 256
#define CHUNK_ROWS 16
#define NCHUNK 9            // 8 full 16-row chunks + one 4-row tail
#define ROW_F4 33           // 132 floats = 33 float4 per row

__device__ __forceinline__ void cp_async16(void* smem_ptr, const void* gptr) {
    uint32_t s = (uint32_t)__cvta_generic_to_shared(smem_ptr);
    asm volatile("cp.async.cg.shared.global [%0], [%1], 16;\n"
                 :: "r"(s), "l"(gptr));
}
#define CP_COMMIT() asm volatile("cp.async.commit_group;\n" ::: "memory")
#define CP_WAIT1()  asm volatile("cp.async.wait_group 1;\n" ::: "memory")
#define CP_WAIT0()  asm volatile("cp.async.wait_group 0;\n" ::: "memory")

__global__ __launch_bounds__(NTHREADS)
void gate_kernel(const float* __restrict__ in,
                 const int*  __restrict__ enabled,
                 float* __restrict__ out)
{
    const int bc = blockIdx.x;
    const long long base = (long long)bc * NPIX;
    const int tid  = threadIdx.x;
    const int warp = tid >> 5;
    const int lane = tid & 31;

    if (*enabled == 0) {
        float4 ones = make_float4(1.f, 1.f, 1.f, 1.f);
        float4* o4 = (float4*)(out + base);
        for (int p = tid; p < NPIX / 4; p += NTHREADS) o4[p] = ones;
        return;
    }

    __shared__ float4 buf[2][CHUNK_ROWS * ROW_F4];   // staging, 2 x 8448 B
    __shared__ float  rbs[HH * NBX];                 // per-row block partials
    __shared__ float  pooled[NBLK];
    __shared__ float  hardm[NBLK];
    __shared__ int    hist[32];
    __shared__ float  wmin[8], wmax[8];
    __shared__ float  s_minv, s_scale;
    __shared__ int    s_bb, s_chi, s_mcnt;
    __shared__ int    bblist[NBLK];

    if (tid < 32) hist[tid] = 0;
    if (tid == 0) s_mcnt = 0;

    const float4* src4 = (const float4*)(in + base);

    // ---- Phase A: double-buffered cp.async staging + smem reduction.
    // stage chunk 0
    {
        int nr = CHUNK_ROWS;                         // chunk 0 is full
        int n4 = nr * ROW_F4;
        for (int i = tid; i < n4; i += NTHREADS)
            cp_async16(&buf[0][i], src4 + i);
        CP_COMMIT();
    }
    for (int c = 0; c < NCHUNK; c++) {
        int r0 = c * CHUNK_ROWS;
        int nr = min(CHUNK_ROWS, HH - r0);
        if (c + 1 < NCHUNK) {
            int r0n = (c + 1) * CHUNK_ROWS;
            int nrn = min(CHUNK_ROWS, HH - r0n);
            int n4  = nrn * ROW_F4;
            const float4* g = src4 + r0n * ROW_F4;
            float4* b = buf[(c + 1) & 1];
            for (int i = tid; i < n4; i += NTHREADS)
                cp_async16(&b[i], g + i);
            CP_COMMIT();
            CP_WAIT1();
        } else {
            CP_WAIT0();
        }
        __syncthreads();

        // consume chunk c: per-(row, bx) partial with the canonical tree
        const float* bf = (const float*)buf[c & 1];
        int tasks = nr * NBX;
        for (int t = tid; t < tasks; t += NTHREADS) {
            int rl = t / NBX;
            int bx = t - rl * NBX;
            const float* row = bf + rl * WW;
            float4 a = *(const float4*)(row + bx * 8);
            float4 b4;
            if (bx < 16) b4 = *(const float4*)(row + bx * 8 + 4);
            else         b4 = make_float4(0.f, 0.f, 0.f, 0.f);
            rbs[(r0 + rl) * NBX + bx] =
                  ((fabsf(a.x) + fabsf(b4.x)) + (fabsf(a.z) + fabsf(b4.z)))
                + ((fabsf(a.y) + fabsf(b4.y)) + (fabsf(a.w) + fabsf(b4.w)));
        }
        __syncthreads();
    }

    // ---- Phase B: block sums (linear over 8 rows, rows>=132 are pad) + min/max.
    float lmin = 3.4e38f, lmax = -3.4e38f;
    for (int b = tid; b < NBLK; b += NTHREADS) {
        int by = b / NBX;
        int bx = b - by * NBX;
        int y0 = by * 8;
        float s = 0.0f;
        #pragma unroll
        for (int r = 0; r < 8; r++) {
            int y = y0 + r;
            if (y < HH) s += rbs[y * NBX + bx];
        }
        pooled[b] = s;
        lmin = fminf(lmin, s);
        lmax = fmaxf(lmax, s);
    }
    #pragma unroll
    for (int off = 16; off > 0; off >>= 1) {
        lmin = fminf(lmin, __shfl_down_sync(0xffffffffu, lmin, off));
        lmax = fmaxf(lmax, __shfl_down_sync(0xffffffffu, lmax, off));
    }
    if (lane == 0) { wmin[warp] = lmin; wmax[warp] = lmax; }
    __syncthreads();

    // ---- warp 0: global min/max -> bin scale
    if (warp == 0) {
        float mn = (lane < 8) ? wmin[lane] : 3.4e38f;
        float mx = (lane < 8) ? wmax[lane] : -3.4e38f;
        #pragma unroll
        for (int off = 4; off > 0; off >>= 1) {
            mn = fminf(mn, __shfl_down_sync(0xffffffffu, mn, off));
            mx = fmaxf(mx, __shfl_down_sync(0xffffffffu, mx, off));
        }
        if (lane == 0) {
            float r = mx - mn;
            s_minv  = mn;
            s_scale = (r > 0.0f) ? (32.0f / r) : 0.0f;
        }
    }
    __syncthreads();

    // ---- histogram
    {
        float minv = s_minv, scale = s_scale;
        for (int b = tid; b < NBLK; b += NTHREADS) {
            int bin = min((int)((pooled[b] - minv) * scale), 31);
            atomicAdd(&hist[bin], 1);
        }
    }
    __syncthreads();

    // ---- warp 0: suffix scan -> boundary bin bb, count strictly above (chi)
    if (warp == 0) {
        int cge = hist[lane];
        #pragma unroll
        for (int off = 1; off < 32; off <<= 1) {
            int t = __shfl_down_sync(0xffffffffu, cge, off);
            if (lane + off < 32) cge += t;
        }
        int cgt = __shfl_down_sync(0xffffffffu, cge, 1);
        if (lane == 31) cgt = 0;
        if (cgt < KEEP && cge >= KEEP) { s_bb = lane; s_chi = cgt; }
    }
    __syncthreads();

    // ---- classify; collect boundary-bin items
    {
        float minv = s_minv, scale = s_scale;
        int bb = s_bb;
        for (int b = tid; b < NBLK; b += NTHREADS) {
            int bin = min((int)((pooled[b] - minv) * scale), 31);
            if (bin > bb)      hardm[b] = 1.0f;
            else if (bin < bb) hardm[b] = 0.0f;
            else               bblist[atomicAdd(&s_mcnt, 1)] = b;
        }
    }
    __syncthreads();

    // ---- exact rank inside boundary bin (tie: lower index wins)
    {
        int m = s_mcnt;
        int budget = KEEP - s_chi;
        for (int it = tid; it < m; it += NTHREADS) {
            int i = bblist[it];
            float vi = pooled[i];
            int c = 0;
            for (int j = 0; j < m; j++) {
                int jj = bblist[j];
                float vj = pooled[jj];
                c += (vj > vi) || (vj == vi && jj < i);
            }
            hardm[i] = (c < budget) ? 1.0f : 0.0f;
        }
    }
    __syncthreads();

    // ---- Phase D: expand to pixels, float4 stores
    for (int by = warp; by < NBX; by += 8) {
        float  mv  = hardm[by * NBX + (lane >> 1)];
        float  m16 = hardm[by * NBX + 16];
        float4 v4  = make_float4(mv, mv, mv, mv);
        float4 v16 = make_float4(m16, m16, m16, m16);
        int ylim = min(HH - by * 8, 8);
        float* obase = out + base + (by * 8) * WW;
        for (int r = 0; r < ylim; r++) {
            float* orow = obase + r * WW;
            *(float4*)(orow + lane * 4) = v4;
            if (lane == 0) *(float4*)(orow + 128) = v16;
        }
    }
}

extern "C" void kernel_launch(void* const* d_in, const int* in_sizes, int n_in,
                              void* d_out, int out_size)
{
    const float* features = (const float*)d_in[0];
    const int*   enabled  = (const int*)d_in[1];
    float* out = (float*)d_out;

    const int n_channels = out_size / NPIX;   // 2048
    gate_kernel<<<n_channels, NTHREADS>>>(features, enabled, out);
}